// round 1
// baseline (speedup 1.0000x reference)
#include <cuda_runtime.h>
#include <math.h>

#define EN_MAX 200000
#define TN_MAX 600000
#define HH 128
#define IC 64
#define BSZ 8
#define NRAD 6
#define SBFK 42
#define TK 294

// ---------------- scratch (device globals; no allocations) ----------------
__device__ float g_xji[EN_MAX * HH];
__device__ float g_rbfh[EN_MAX * HH];
__device__ float g_rbfh2[EN_MAX * HH];
__device__ float g_rb8[EN_MAX * BSZ];
__device__ float g_xdown[EN_MAX * IC];
__device__ float g_acc[EN_MAX * IC];
__device__ float g_t8[TN_MAX * BSZ];
__device__ float g_s8[TN_MAX * BSZ];
__device__ float g_bufA[EN_MAX * HH];
__device__ float g_bufB[EN_MAX * HH];
__device__ float g_bufC[EN_MAX * HH];

__device__ __forceinline__ float silu_f(float x) {
    return x / (1.0f + __expf(-x));
}

// ---------------- generic row-wise GEMM + epilogue ----------------
// out[row, j] = epi( sum_k in[row,k] * W[k,j] )
// epilogue: (+bias) -> (silu if act) -> (*mulv) -> (+addv); optional second
// output out2 = out * mul2.
// blockDim.x == NOUT threads; each block handles 64 rows in groups of 8.
// W is staged transposed, per-thread-private rows in dynamic smem.
template <int KIN, int NOUT>
__global__ void gemm_rows(const float* __restrict__ in,
                          const float* __restrict__ W,
                          const float* __restrict__ bias,
                          const float* __restrict__ mulv,
                          const float* __restrict__ addv,
                          float* __restrict__ out,
                          const float* __restrict__ mul2,
                          float* __restrict__ out2,
                          int nrows, int act)
{
    constexpr int PITCH = KIN + 4;
    extern __shared__ float sm[];
    float* Wt = sm;                                       // NOUT * PITCH floats
    float4* xsA = reinterpret_cast<float4*>(sm + NOUT * PITCH);   // KIN float4 (rows 0..3)
    float4* xsB = xsA + KIN;                                      // KIN float4 (rows 4..7)

    const int j = threadIdx.x;

    // stage W transposed: thread j owns row j of Wt (only it reads it -> no sync needed for W)
    #pragma unroll 4
    for (int k = 0; k < KIN; ++k)
        Wt[j * PITCH + k] = W[(size_t)k * NOUT + j];

    const float bj = bias ? bias[j] : 0.0f;
    const float4* wt4 = reinterpret_cast<const float4*>(Wt + j * PITCH);

    const int row0 = blockIdx.x * 64;

    for (int g = 0; g < 8; ++g) {
        const int r = row0 + g * 8;
        if (r >= nrows) break;
        __syncthreads();
        // stage 8 rows of input, interleaved by k
        for (int k = j; k < KIN; k += NOUT) {
            float4 va, vb;
            va.x = in[(size_t)(r + 0) * KIN + k];
            va.y = in[(size_t)(r + 1) * KIN + k];
            va.z = in[(size_t)(r + 2) * KIN + k];
            va.w = in[(size_t)(r + 3) * KIN + k];
            vb.x = in[(size_t)(r + 4) * KIN + k];
            vb.y = in[(size_t)(r + 5) * KIN + k];
            vb.z = in[(size_t)(r + 6) * KIN + k];
            vb.w = in[(size_t)(r + 7) * KIN + k];
            xsA[k] = va;
            xsB[k] = vb;
        }
        __syncthreads();

        float a0 = 0.f, a1 = 0.f, a2 = 0.f, a3 = 0.f;
        float a4 = 0.f, a5 = 0.f, a6 = 0.f, a7 = 0.f;
        #pragma unroll 8
        for (int k4 = 0; k4 < KIN / 4; ++k4) {
            const float4 w = wt4[k4];
            float4 x;
            x = xsA[k4 * 4 + 0]; a0 += w.x * x.x; a1 += w.x * x.y; a2 += w.x * x.z; a3 += w.x * x.w;
            x = xsB[k4 * 4 + 0]; a4 += w.x * x.x; a5 += w.x * x.y; a6 += w.x * x.z; a7 += w.x * x.w;
            x = xsA[k4 * 4 + 1]; a0 += w.y * x.x; a1 += w.y * x.y; a2 += w.y * x.z; a3 += w.y * x.w;
            x = xsB[k4 * 4 + 1]; a4 += w.y * x.x; a5 += w.y * x.y; a6 += w.y * x.z; a7 += w.y * x.w;
            x = xsA[k4 * 4 + 2]; a0 += w.z * x.x; a1 += w.z * x.y; a2 += w.z * x.z; a3 += w.z * x.w;
            x = xsB[k4 * 4 + 2]; a4 += w.z * x.x; a5 += w.z * x.y; a6 += w.z * x.z; a7 += w.z * x.w;
            x = xsA[k4 * 4 + 3]; a0 += w.w * x.x; a1 += w.w * x.y; a2 += w.w * x.z; a3 += w.w * x.w;
            x = xsB[k4 * 4 + 3]; a4 += w.w * x.x; a5 += w.w * x.y; a6 += w.w * x.z; a7 += w.w * x.w;
        }

        float ys[8] = {a0, a1, a2, a3, a4, a5, a6, a7};
        #pragma unroll
        for (int rr = 0; rr < 8; ++rr) {
            const size_t o = (size_t)(r + rr) * NOUT + j;
            float v = ys[rr] + bj;
            if (act) v = silu_f(v);
            if (mulv) v *= mulv[o];
            if (addv) v += addv[o];
            out[o] = v;
            if (out2) out2[o] = v * mul2[o];
        }
    }
}

// ---------------- rbf basis helpers ----------------
__global__ void rb8_kernel(const float* __restrict__ rbf, const float* __restrict__ W1,
                           float* __restrict__ out, int n)
{
    const int e = blockIdx.x * blockDim.x + threadIdx.x;
    if (e >= n) return;
    float r[NRAD];
    #pragma unroll
    for (int i = 0; i < NRAD; ++i) r[i] = rbf[(size_t)e * NRAD + i];
    #pragma unroll
    for (int b = 0; b < BSZ; ++b) {
        float s = 0.f;
        #pragma unroll
        for (int i = 0; i < NRAD; ++i) s += r[i] * __ldg(&W1[i * BSZ + b]);
        out[(size_t)e * BSZ + b] = s;
    }
}

// rbfh[e,j]  = sum_b rb8[e,b]  * W_rbf2[b,j]
// rbfh2[e,j] = sum_r rbf[e,r]  * W_rbf[r,j]
__global__ void rbfh_kernel(const float* __restrict__ rb8, const float* __restrict__ rbf,
                            const float* __restrict__ W_rbf2, const float* __restrict__ W_rbf,
                            float* __restrict__ rbfh, float* __restrict__ rbfh2, int n)
{
    __shared__ float w2[BSZ * HH];
    __shared__ float wr[NRAD * HH];
    const int j = threadIdx.x;
    #pragma unroll
    for (int b = 0; b < BSZ; ++b) w2[b * HH + j] = W_rbf2[b * HH + j];
    #pragma unroll
    for (int r = 0; r < NRAD; ++r) wr[r * HH + j] = W_rbf[r * HH + j];
    __syncthreads();

    const int row0 = blockIdx.x * 32;
    for (int rr = 0; rr < 32; ++rr) {
        const int row = row0 + rr;
        if (row >= n) return;
        const float4* rp = reinterpret_cast<const float4*>(rb8 + (size_t)row * BSZ);
        const float4 ra = __ldg(rp), rb = __ldg(rp + 1);
        float a1 = ra.x * w2[0 * HH + j] + ra.y * w2[1 * HH + j] +
                   ra.z * w2[2 * HH + j] + ra.w * w2[3 * HH + j] +
                   rb.x * w2[4 * HH + j] + rb.y * w2[5 * HH + j] +
                   rb.z * w2[6 * HH + j] + rb.w * w2[7 * HH + j];
        float a2 = 0.f;
        #pragma unroll
        for (int r = 0; r < NRAD; ++r) a2 += __ldg(&rbf[(size_t)row * NRAD + r]) * wr[r * HH + j];
        rbfh[(size_t)row * HH + j]  = a1;
        rbfh2[(size_t)row * HH + j] = a2;
    }
}

// ---------------- T-space: X[T,K] @ W1[K,8] -> out8[T,8] ----------------
// warp handles 4 rows; lane-strided coalesced global reads of X;
// column-major W in smem (conflict-free); smem-based cross-lane reduction.
template <int K, int PK>
__global__ void proj8_kernel(const float* __restrict__ X, const float* __restrict__ W1,
                             float* __restrict__ out8, int nrows)
{
    __shared__ float wcm[BSZ * PK];
    __shared__ float red[8][32 * 33];
    const int tid = threadIdx.x;
    for (int x = tid; x < BSZ * PK; x += blockDim.x) wcm[x] = 0.f;
    __syncthreads();
    for (int x = tid; x < K * BSZ; x += blockDim.x) {
        const int i = x / BSZ, b = x % BSZ;
        wcm[b * PK + i] = W1[x];
    }
    __syncthreads();

    const int warp = tid >> 5, lane = tid & 31;
    float* myred = &red[warp][0];
    const int nw = blockDim.x >> 5;
    constexpr int ITERS = (K + 31) / 32;

    for (int r0 = (blockIdx.x * nw + warp) * 4; r0 < nrows; r0 += gridDim.x * nw * 4) {
        float acc[4][BSZ] = {};
        const float* x0 = X + (size_t)r0 * K;
        #pragma unroll
        for (int k = 0; k < ITERS; ++k) {
            const int i = lane + k * 32;
            float xv[4] = {0.f, 0.f, 0.f, 0.f};
            if (i < K) {
                #pragma unroll
                for (int rr = 0; rr < 4; ++rr) xv[rr] = x0[(size_t)rr * K + i];
            }
            #pragma unroll
            for (int b = 0; b < BSZ; ++b) {
                const float w = wcm[b * PK + i];
                #pragma unroll
                for (int rr = 0; rr < 4; ++rr) acc[rr][b] += w * xv[rr];
            }
        }
        // cross-lane reduce via smem: value v = rr*8+b, lane v reduces column v
        #pragma unroll
        for (int rr = 0; rr < 4; ++rr)
            #pragma unroll
            for (int b = 0; b < BSZ; ++b)
                myred[lane * 33 + rr * BSZ + b] = acc[rr][b];
        __syncwarp();
        float s = 0.f;
        #pragma unroll
        for (int l = 0; l < 32; ++l) s += myred[l * 33 + lane];
        out8[(size_t)r0 * BSZ + lane] = s;   // coalesced: r0*8 + lane covers 4 rows x 8
        __syncwarp();
    }
}

// ---------------- triplet gather/scale/scatter ----------------
__global__ void triplet_kernel(const float* __restrict__ t8, const float* __restrict__ s8,
                               const float* __restrict__ W_t2, const float* __restrict__ W_sbf2,
                               const float* __restrict__ xdown,
                               const int* __restrict__ idx_kj, const int* __restrict__ idx_ji,
                               float* __restrict__ acc, int nt)
{
    __shared__ float wt2s[BSZ * IC];
    __shared__ float ws2s[BSZ * IC];
    const int tid = threadIdx.x;
    for (int i = tid; i < BSZ * IC; i += blockDim.x) { wt2s[i] = W_t2[i]; ws2s[i] = W_sbf2[i]; }
    __syncthreads();

    const int warp = tid >> 5, lane = tid & 31;
    const int total_warps = (blockDim.x * gridDim.x) >> 5;

    for (int tr = blockIdx.x * (blockDim.x >> 5) + warp; tr < nt; tr += total_warps) {
        const float4* tp = reinterpret_cast<const float4*>(t8 + (size_t)tr * BSZ);
        const float4 ta = __ldg(tp), tb = __ldg(tp + 1);
        const float4* sp = reinterpret_cast<const float4*>(s8 + (size_t)tr * BSZ);
        const float4 sa = __ldg(sp), sb = __ldg(sp + 1);
        const float tv[BSZ] = {ta.x, ta.y, ta.z, ta.w, tb.x, tb.y, tb.z, tb.w};
        const float sv[BSZ] = {sa.x, sa.y, sa.z, sa.w, sb.x, sb.y, sb.z, sb.w};
        const int kj = idx_kj[tr], ji = idx_ji[tr];
        const int c0 = lane, c1 = lane + 32;
        float t0 = 0.f, t1 = 0.f, s0 = 0.f, s1 = 0.f;
        #pragma unroll
        for (int b = 0; b < BSZ; ++b) {
            t0 += tv[b] * wt2s[b * IC + c0];
            t1 += tv[b] * wt2s[b * IC + c1];
            s0 += sv[b] * ws2s[b * IC + c0];
            s1 += sv[b] * ws2s[b * IC + c1];
        }
        const float g0 = xdown[(size_t)kj * IC + c0];
        const float g1 = xdown[(size_t)kj * IC + c1];
        atomicAdd(acc + (size_t)ji * IC + c0, g0 * t0 * s0);
        atomicAdd(acc + (size_t)ji * IC + c1, g1 * t1 * s1);
    }
}

__global__ void zero4_kernel(float4* __restrict__ p, int n4)
{
    const int i = blockIdx.x * blockDim.x + threadIdx.x;
    if (i < n4) p[i] = make_float4(0.f, 0.f, 0.f, 0.f);
}

// ---------------- launch ----------------
extern "C" void kernel_launch(void* const* d_in, const int* in_sizes, int n_in,
                              void* d_out, int out_size)
{
    const float* e1     = (const float*)d_in[0];
    const float* rbf    = (const float*)d_in[1];
    const float* sbf    = (const float*)d_in[2];
    const float* tt     = (const float*)d_in[3];
    const int*   idx_kj = (const int*)d_in[4];
    const int*   idx_ji = (const int*)d_in[5];
    const float* W_rbf1 = (const float*)d_in[6];
    const float* W_rbf2 = (const float*)d_in[7];
    const float* W_sbf1 = (const float*)d_in[8];
    const float* W_sbf2 = (const float*)d_in[9];
    const float* W_t1   = (const float*)d_in[10];
    const float* W_t2   = (const float*)d_in[11];
    const float* W_rbf  = (const float*)d_in[12];
    const float* W_kj   = (const float*)d_in[13];
    const float* b_kj   = (const float*)d_in[14];
    const float* W_ji   = (const float*)d_in[15];
    const float* b_ji   = (const float*)d_in[16];
    const float* W_down = (const float*)d_in[17];
    const float* W_up   = (const float*)d_in[18];
    const float* Wb1    = (const float*)d_in[19];
    const float* bb1    = (const float*)d_in[20];
    const float* Wb2    = (const float*)d_in[21];
    const float* bb2    = (const float*)d_in[22];
    const float* W_lin  = (const float*)d_in[23];
    const float* b_lin  = (const float*)d_in[24];
    const float* Wa1    = (const float*)d_in[25];
    const float* ba1    = (const float*)d_in[26];
    const float* Wa2    = (const float*)d_in[27];
    const float* ba2    = (const float*)d_in[28];

    const int E = in_sizes[0] / HH;
    const int T = in_sizes[4];

    float *xji, *rbfh, *rbfh2, *rb8, *xdown, *acc, *t8, *s8, *A, *B, *C;
    cudaGetSymbolAddress((void**)&xji,   g_xji);
    cudaGetSymbolAddress((void**)&rbfh,  g_rbfh);
    cudaGetSymbolAddress((void**)&rbfh2, g_rbfh2);
    cudaGetSymbolAddress((void**)&rb8,   g_rb8);
    cudaGetSymbolAddress((void**)&xdown, g_xdown);
    cudaGetSymbolAddress((void**)&acc,   g_acc);
    cudaGetSymbolAddress((void**)&t8,    g_t8);
    cudaGetSymbolAddress((void**)&s8,    g_s8);
    cudaGetSymbolAddress((void**)&A,     g_bufA);
    cudaGetSymbolAddress((void**)&B,     g_bufB);
    cudaGetSymbolAddress((void**)&C,     g_bufC);

    float* out_e1 = (float*)d_out;
    float* out_e2 = (float*)d_out + (size_t)E * HH;

    // dynamic smem sizes per GEMM instance
    const int sm_128_128 = (HH * (HH + 4)) * 4 + HH * 32;   // 67584 + 4096 = 71680
    const int sm_128_64  = (IC * (HH + 4)) * 4 + HH * 32;   // 33792 + 4096 = 37888
    const int sm_64_128  = (HH * (IC + 4)) * 4 + IC * 32;   // 34816 + 2048 = 36864
    cudaFuncSetAttribute(gemm_rows<HH, HH>, cudaFuncAttributeMaxDynamicSharedMemorySize, sm_128_128);
    cudaFuncSetAttribute(gemm_rows<HH, IC>, cudaFuncAttributeMaxDynamicSharedMemorySize, sm_128_64);
    cudaFuncSetAttribute(gemm_rows<IC, HH>, cudaFuncAttributeMaxDynamicSharedMemorySize, sm_64_128);

    const int gblocks = (E + 63) / 64;

    // rbf basis paths
    rb8_kernel<<<(E + 255) / 256, 256>>>(rbf, W_rbf1, rb8, E);
    rbfh_kernel<<<(E + 31) / 32, HH>>>(rb8, rbf, W_rbf2, W_rbf, rbfh, rbfh2, E);

    // x_ji = silu(e1 @ W_ji + b_ji)
    gemm_rows<HH, HH><<<gblocks, HH, sm_128_128>>>(e1, W_ji, b_ji, nullptr, nullptr, xji, nullptr, nullptr, E, 1);
    // A = silu(e1 @ W_kj + b_kj) * rbfh
    gemm_rows<HH, HH><<<gblocks, HH, sm_128_128>>>(e1, W_kj, b_kj, rbfh, nullptr, A, nullptr, nullptr, E, 1);
    // xdown = silu(A @ W_down)
    gemm_rows<HH, IC><<<gblocks, IC, sm_128_64>>>(A, W_down, nullptr, nullptr, nullptr, xdown, nullptr, nullptr, E, 1);

    // zero accumulator
    zero4_kernel<<<(E * IC / 4 + 255) / 256, 256>>>((float4*)acc, E * IC / 4);

    // T-space projections
    proj8_kernel<TK, 320><<<2048, 256>>>(tt, W_t1, t8, T);
    proj8_kernel<SBFK, 64><<<2048, 256>>>(sbf, W_sbf1, s8, T);

    // gather * sbf_h * t_h, scatter-add by idx_ji
    triplet_kernel<<<2368, 256>>>(t8, s8, W_t2, W_sbf2, xdown, idx_kj, idx_ji, acc, T);

    // A = silu(acc @ W_up) + x_ji
    gemm_rows<IC, HH><<<gblocks, HH, sm_64_128>>>(acc, W_up, nullptr, nullptr, xji, A, nullptr, nullptr, E, 1);

    // residual before (1 layer)
    gemm_rows<HH, HH><<<gblocks, HH, sm_128_128>>>(A, Wb1, bb1, nullptr, nullptr, B, nullptr, nullptr, E, 1);
    gemm_rows<HH, HH><<<gblocks, HH, sm_128_128>>>(B, Wb2, bb2, nullptr, A, C, nullptr, nullptr, E, 1);

    // h = silu(C @ W_lin + b_lin) + e1
    gemm_rows<HH, HH><<<gblocks, HH, sm_128_128>>>(C, W_lin, b_lin, nullptr, e1, A, nullptr, nullptr, E, 1);

    // residual after layer 0
    gemm_rows<HH, HH><<<gblocks, HH, sm_128_128>>>(A, Wa1, ba1, nullptr, nullptr, B, nullptr, nullptr, E, 1);
    gemm_rows<HH, HH><<<gblocks, HH, sm_128_128>>>(B, Wa2, ba2, nullptr, A, C, nullptr, nullptr, E, 1);
    // residual after layer 1 -> final outputs (e1_out, e2_out = e1_out * rbfh2)
    gemm_rows<HH, HH><<<gblocks, HH, sm_128_128>>>(C, Wa1 + HH * HH, ba1 + HH, nullptr, nullptr, B, nullptr, nullptr, E, 1);
    gemm_rows<HH, HH><<<gblocks, HH, sm_128_128>>>(B, Wa2 + HH * HH, ba2 + HH, nullptr, C, out_e1, rbfh2, out_e2, E, 1);
}

// round 2
// speedup vs baseline: 1.8158x; 1.8158x over previous
#include <cuda_runtime.h>
#include <math.h>

#define EN_MAX 200000
#define TN_MAX 600000
#define HH 128
#define IC 64
#define BSZ 8
#define NRAD 6
#define SBFK 42
#define TK 294

// ---------------- scratch (device globals; no allocations) ----------------
__device__ float g_xji[EN_MAX * HH];
__device__ float g_rbfh[EN_MAX * HH];
__device__ float g_rbfh2[EN_MAX * HH];
__device__ float g_rb8[EN_MAX * BSZ];
__device__ float g_xdown[EN_MAX * IC];
__device__ float g_acc[EN_MAX * IC];
__device__ float g_t8[TN_MAX * BSZ];
__device__ float g_s8[TN_MAX * BSZ];
__device__ float g_bufA[EN_MAX * HH];
__device__ float g_bufB[EN_MAX * HH];
__device__ float g_bufC[EN_MAX * HH];

__device__ __forceinline__ float silu_f(float x) {
    return x / (1.0f + __expf(-x));
}

// ---------------- register-tiled row-wise GEMM + epilogue ----------------
// out[row, j] = epi( sum_k in[row,k] * W[k,j] )
// Block computes a 128 x NOUT tile; each thread an 8x8 register tile.
// Per k-step a thread does 4x LDS.128 feeding 64 FFMAs -> FMA-bound.
template <int KIN, int NOUT>
__global__ void __launch_bounds__(NOUT * 2, 2)
gemm_rt(const float* __restrict__ in,
        const float* __restrict__ W,
        const float* __restrict__ bias,
        const float* __restrict__ mulv,
        const float* __restrict__ addv,
        float* __restrict__ out,
        const float* __restrict__ mul2,
        float* __restrict__ out2,
        int nrows, int act)
{
    constexpr int THREADS = NOUT * 2;        // 256 (NOUT=128) or 128 (NOUT=64)
    constexpr int KB = 64;                   // k-chunk
    constexpr int NC = KIN / KB;             // 2 or 1
    constexpr int APITCH = 132;              // 16B-aligned pad, avoids STS conflicts mostly
    constexpr int TPR = THREADS / 128;       // threads per staged A row
    constexpr int KSPAN = KB / TPR;          // floats per thread per A row

    extern __shared__ float sm[];
    float* As = sm;                          // [KB][APITCH] k-major
    float* Bs = sm + KB * APITCH;            // [KB][NOUT]

    const int tid = threadIdx.x;
    const int tr = tid / (NOUT / 8);         // thread row group (0..15)
    const int tc = tid % (NOUT / 8);         // thread col group
    const int r0 = blockIdx.x * 128;

    float acc[8][8] = {};

    #pragma unroll
    for (int c = 0; c < NC; ++c) {
        const int c0 = c * KB;
        if (c) __syncthreads();

        // stage A chunk transposed (k-major)
        {
            const int row = tid / TPR;
            const int part = tid % TPR;
            int rclamp = r0 + row;
            if (rclamp >= nrows) rclamp = nrows - 1;
            const float* src = in + (size_t)rclamp * KIN + c0 + part * KSPAN;
            #pragma unroll
            for (int f = 0; f < KSPAN / 4; ++f) {
                const float4 v = *reinterpret_cast<const float4*>(src + f * 4);
                const int kk = part * KSPAN + f * 4;
                As[(kk + 0) * APITCH + row] = v.x;
                As[(kk + 1) * APITCH + row] = v.y;
                As[(kk + 2) * APITCH + row] = v.z;
                As[(kk + 3) * APITCH + row] = v.w;
            }
        }
        // stage B chunk (direct copy, row-major [KB][NOUT])
        {
            const float4* Wsrc = reinterpret_cast<const float4*>(W + (size_t)c0 * NOUT);
            float4* Bd = reinterpret_cast<float4*>(Bs);
            #pragma unroll
            for (int i = tid; i < KB * NOUT / 4; i += THREADS)
                Bd[i] = Wsrc[i];
        }
        __syncthreads();

        #pragma unroll 4
        for (int k = 0; k < KB; ++k) {
            const float4 a0 = *reinterpret_cast<const float4*>(&As[k * APITCH + tr * 8]);
            const float4 a1 = *reinterpret_cast<const float4*>(&As[k * APITCH + tr * 8 + 4]);
            const float4 b0 = *reinterpret_cast<const float4*>(&Bs[k * NOUT + tc * 8]);
            const float4 b1 = *reinterpret_cast<const float4*>(&Bs[k * NOUT + tc * 8 + 4]);
            const float a[8] = {a0.x, a0.y, a0.z, a0.w, a1.x, a1.y, a1.z, a1.w};
            const float b[8] = {b0.x, b0.y, b0.z, b0.w, b1.x, b1.y, b1.z, b1.w};
            #pragma unroll
            for (int i = 0; i < 8; ++i)
                #pragma unroll
                for (int j = 0; j < 8; ++j)
                    acc[i][j] += a[i] * b[j];
        }
    }

    // epilogue
    float bv[8];
    if (bias) {
        const float4 v0 = *reinterpret_cast<const float4*>(bias + tc * 8);
        const float4 v1 = *reinterpret_cast<const float4*>(bias + tc * 8 + 4);
        bv[0]=v0.x; bv[1]=v0.y; bv[2]=v0.z; bv[3]=v0.w;
        bv[4]=v1.x; bv[5]=v1.y; bv[6]=v1.z; bv[7]=v1.w;
    } else {
        #pragma unroll
        for (int j = 0; j < 8; ++j) bv[j] = 0.f;
    }

    #pragma unroll
    for (int i = 0; i < 8; ++i) {
        const int row = r0 + tr * 8 + i;
        if (row >= nrows) break;
        const size_t o = (size_t)row * NOUT + tc * 8;
        float v[8];
        #pragma unroll
        for (int j = 0; j < 8; ++j) {
            float x = acc[i][j] + bv[j];
            if (act) x = silu_f(x);
            v[j] = x;
        }
        if (mulv) {
            const float4 m0 = *reinterpret_cast<const float4*>(mulv + o);
            const float4 m1 = *reinterpret_cast<const float4*>(mulv + o + 4);
            v[0]*=m0.x; v[1]*=m0.y; v[2]*=m0.z; v[3]*=m0.w;
            v[4]*=m1.x; v[5]*=m1.y; v[6]*=m1.z; v[7]*=m1.w;
        }
        if (addv) {
            const float4 s0 = *reinterpret_cast<const float4*>(addv + o);
            const float4 s1 = *reinterpret_cast<const float4*>(addv + o + 4);
            v[0]+=s0.x; v[1]+=s0.y; v[2]+=s0.z; v[3]+=s0.w;
            v[4]+=s1.x; v[5]+=s1.y; v[6]+=s1.z; v[7]+=s1.w;
        }
        *reinterpret_cast<float4*>(out + o)     = make_float4(v[0], v[1], v[2], v[3]);
        *reinterpret_cast<float4*>(out + o + 4) = make_float4(v[4], v[5], v[6], v[7]);
        if (out2) {
            const float4 m0 = *reinterpret_cast<const float4*>(mul2 + o);
            const float4 m1 = *reinterpret_cast<const float4*>(mul2 + o + 4);
            *reinterpret_cast<float4*>(out2 + o)     = make_float4(v[0]*m0.x, v[1]*m0.y, v[2]*m0.z, v[3]*m0.w);
            *reinterpret_cast<float4*>(out2 + o + 4) = make_float4(v[4]*m1.x, v[5]*m1.y, v[6]*m1.z, v[7]*m1.w);
        }
    }
}

// ---------------- rbf basis helpers ----------------
__global__ void rb8_kernel(const float* __restrict__ rbf, const float* __restrict__ W1,
                           float* __restrict__ out, int n)
{
    const int e = blockIdx.x * blockDim.x + threadIdx.x;
    if (e >= n) return;
    float r[NRAD];
    #pragma unroll
    for (int i = 0; i < NRAD; ++i) r[i] = rbf[(size_t)e * NRAD + i];
    #pragma unroll
    for (int b = 0; b < BSZ; ++b) {
        float s = 0.f;
        #pragma unroll
        for (int i = 0; i < NRAD; ++i) s += r[i] * __ldg(&W1[i * BSZ + b]);
        out[(size_t)e * BSZ + b] = s;
    }
}

__global__ void rbfh_kernel(const float* __restrict__ rb8, const float* __restrict__ rbf,
                            const float* __restrict__ W_rbf2, const float* __restrict__ W_rbf,
                            float* __restrict__ rbfh, float* __restrict__ rbfh2, int n)
{
    __shared__ float w2[BSZ * HH];
    __shared__ float wr[NRAD * HH];
    const int j = threadIdx.x;
    #pragma unroll
    for (int b = 0; b < BSZ; ++b) w2[b * HH + j] = W_rbf2[b * HH + j];
    #pragma unroll
    for (int r = 0; r < NRAD; ++r) wr[r * HH + j] = W_rbf[r * HH + j];
    __syncthreads();

    const int row0 = blockIdx.x * 32;
    for (int rr = 0; rr < 32; ++rr) {
        const int row = row0 + rr;
        if (row >= n) return;
        const float4* rp = reinterpret_cast<const float4*>(rb8 + (size_t)row * BSZ);
        const float4 ra = __ldg(rp), rb = __ldg(rp + 1);
        float a1 = ra.x * w2[0 * HH + j] + ra.y * w2[1 * HH + j] +
                   ra.z * w2[2 * HH + j] + ra.w * w2[3 * HH + j] +
                   rb.x * w2[4 * HH + j] + rb.y * w2[5 * HH + j] +
                   rb.z * w2[6 * HH + j] + rb.w * w2[7 * HH + j];
        float a2 = 0.f;
        #pragma unroll
        for (int r = 0; r < NRAD; ++r) a2 += __ldg(&rbf[(size_t)row * NRAD + r]) * wr[r * HH + j];
        rbfh[(size_t)row * HH + j]  = a1;
        rbfh2[(size_t)row * HH + j] = a2;
    }
}

// ---------------- T-space: X[T,K] @ W1[K,8] -> out8[T,8] ----------------
template <int K, int PK>
__global__ void proj8_kernel(const float* __restrict__ X, const float* __restrict__ W1,
                             float* __restrict__ out8, int nrows)
{
    __shared__ float wcm[BSZ * PK];
    __shared__ float red[8][32 * 33];
    const int tid = threadIdx.x;
    for (int x = tid; x < BSZ * PK; x += blockDim.x) wcm[x] = 0.f;
    __syncthreads();
    for (int x = tid; x < K * BSZ; x += blockDim.x) {
        const int i = x / BSZ, b = x % BSZ;
        wcm[b * PK + i] = W1[x];
    }
    __syncthreads();

    const int warp = tid >> 5, lane = tid & 31;
    float* myred = &red[warp][0];
    const int nw = blockDim.x >> 5;
    constexpr int ITERS = (K + 31) / 32;

    for (int r0 = (blockIdx.x * nw + warp) * 4; r0 < nrows; r0 += gridDim.x * nw * 4) {
        float acc[4][BSZ] = {};
        const float* x0 = X + (size_t)r0 * K;
        #pragma unroll
        for (int k = 0; k < ITERS; ++k) {
            const int i = lane + k * 32;
            float xv[4] = {0.f, 0.f, 0.f, 0.f};
            if (i < K) {
                #pragma unroll
                for (int rr = 0; rr < 4; ++rr) xv[rr] = x0[(size_t)rr * K + i];
            }
            #pragma unroll
            for (int b = 0; b < BSZ; ++b) {
                const float w = wcm[b * PK + i];
                #pragma unroll
                for (int rr = 0; rr < 4; ++rr) acc[rr][b] += w * xv[rr];
            }
        }
        #pragma unroll
        for (int rr = 0; rr < 4; ++rr)
            #pragma unroll
            for (int b = 0; b < BSZ; ++b)
                myred[lane * 33 + rr * BSZ + b] = acc[rr][b];
        __syncwarp();
        float s = 0.f;
        #pragma unroll
        for (int l = 0; l < 32; ++l) s += myred[l * 33 + lane];
        out8[(size_t)r0 * BSZ + lane] = s;
        __syncwarp();
    }
}

// ---------------- triplet gather/scale/scatter ----------------
__global__ void triplet_kernel(const float* __restrict__ t8, const float* __restrict__ s8,
                               const float* __restrict__ W_t2, const float* __restrict__ W_sbf2,
                               const float* __restrict__ xdown,
                               const int* __restrict__ idx_kj, const int* __restrict__ idx_ji,
                               float* __restrict__ acc, int nt)
{
    __shared__ float wt2s[BSZ * IC];
    __shared__ float ws2s[BSZ * IC];
    const int tid = threadIdx.x;
    for (int i = tid; i < BSZ * IC; i += blockDim.x) { wt2s[i] = W_t2[i]; ws2s[i] = W_sbf2[i]; }
    __syncthreads();

    const int warp = tid >> 5, lane = tid & 31;
    const int total_warps = (blockDim.x * gridDim.x) >> 5;

    for (int tr = blockIdx.x * (blockDim.x >> 5) + warp; tr < nt; tr += total_warps) {
        const float4* tp = reinterpret_cast<const float4*>(t8 + (size_t)tr * BSZ);
        const float4 ta = __ldg(tp), tb = __ldg(tp + 1);
        const float4* sp = reinterpret_cast<const float4*>(s8 + (size_t)tr * BSZ);
        const float4 sa = __ldg(sp), sb = __ldg(sp + 1);
        const float tv[BSZ] = {ta.x, ta.y, ta.z, ta.w, tb.x, tb.y, tb.z, tb.w};
        const float sv[BSZ] = {sa.x, sa.y, sa.z, sa.w, sb.x, sb.y, sb.z, sb.w};
        const int kj = idx_kj[tr], ji = idx_ji[tr];
        const int c0 = lane, c1 = lane + 32;
        float t0 = 0.f, t1 = 0.f, s0 = 0.f, s1 = 0.f;
        #pragma unroll
        for (int b = 0; b < BSZ; ++b) {
            t0 += tv[b] * wt2s[b * IC + c0];
            t1 += tv[b] * wt2s[b * IC + c1];
            s0 += sv[b] * ws2s[b * IC + c0];
            s1 += sv[b] * ws2s[b * IC + c1];
        }
        const float g0 = xdown[(size_t)kj * IC + c0];
        const float g1 = xdown[(size_t)kj * IC + c1];
        atomicAdd(acc + (size_t)ji * IC + c0, g0 * t0 * s0);
        atomicAdd(acc + (size_t)ji * IC + c1, g1 * t1 * s1);
    }
}

__global__ void zero4_kernel(float4* __restrict__ p, int n4)
{
    const int i = blockIdx.x * blockDim.x + threadIdx.x;
    if (i < n4) p[i] = make_float4(0.f, 0.f, 0.f, 0.f);
}

// ---------------- launch ----------------
extern "C" void kernel_launch(void* const* d_in, const int* in_sizes, int n_in,
                              void* d_out, int out_size)
{
    const float* e1     = (const float*)d_in[0];
    const float* rbf    = (const float*)d_in[1];
    const float* sbf    = (const float*)d_in[2];
    const float* tt     = (const float*)d_in[3];
    const int*   idx_kj = (const int*)d_in[4];
    const int*   idx_ji = (const int*)d_in[5];
    const float* W_rbf1 = (const float*)d_in[6];
    const float* W_rbf2 = (const float*)d_in[7];
    const float* W_sbf1 = (const float*)d_in[8];
    const float* W_sbf2 = (const float*)d_in[9];
    const float* W_t1   = (const float*)d_in[10];
    const float* W_t2   = (const float*)d_in[11];
    const float* W_rbf  = (const float*)d_in[12];
    const float* W_kj   = (const float*)d_in[13];
    const float* b_kj   = (const float*)d_in[14];
    const float* W_ji   = (const float*)d_in[15];
    const float* b_ji   = (const float*)d_in[16];
    const float* W_down = (const float*)d_in[17];
    const float* W_up   = (const float*)d_in[18];
    const float* Wb1    = (const float*)d_in[19];
    const float* bb1    = (const float*)d_in[20];
    const float* Wb2    = (const float*)d_in[21];
    const float* bb2    = (const float*)d_in[22];
    const float* W_lin  = (const float*)d_in[23];
    const float* b_lin  = (const float*)d_in[24];
    const float* Wa1    = (const float*)d_in[25];
    const float* ba1    = (const float*)d_in[26];
    const float* Wa2    = (const float*)d_in[27];
    const float* ba2    = (const float*)d_in[28];

    const int E = in_sizes[0] / HH;
    const int T = in_sizes[4];

    float *xji, *rbfh, *rbfh2, *rb8, *xdown, *acc, *t8, *s8, *A, *B, *C;
    cudaGetSymbolAddress((void**)&xji,   g_xji);
    cudaGetSymbolAddress((void**)&rbfh,  g_rbfh);
    cudaGetSymbolAddress((void**)&rbfh2, g_rbfh2);
    cudaGetSymbolAddress((void**)&rb8,   g_rb8);
    cudaGetSymbolAddress((void**)&xdown, g_xdown);
    cudaGetSymbolAddress((void**)&acc,   g_acc);
    cudaGetSymbolAddress((void**)&t8,    g_t8);
    cudaGetSymbolAddress((void**)&s8,    g_s8);
    cudaGetSymbolAddress((void**)&A,     g_bufA);
    cudaGetSymbolAddress((void**)&B,     g_bufB);
    cudaGetSymbolAddress((void**)&C,     g_bufC);

    float* out_e1 = (float*)d_out;
    float* out_e2 = (float*)d_out + (size_t)E * HH;

    // dynamic smem: As[64][132] + Bs[64][NOUT]
    const int sm_g128 = 64 * 132 * 4 + 64 * 128 * 4;   // 66560
    const int sm_gd   = 64 * 132 * 4 + 64 * 64 * 4;    // 50176
    const int sm_gu   = 64 * 132 * 4 + 64 * 128 * 4;   // 66560
    cudaFuncSetAttribute(gemm_rt<HH, HH>, cudaFuncAttributeMaxDynamicSharedMemorySize, sm_g128);
    cudaFuncSetAttribute(gemm_rt<HH, IC>, cudaFuncAttributeMaxDynamicSharedMemorySize, sm_gd);
    cudaFuncSetAttribute(gemm_rt<IC, HH>, cudaFuncAttributeMaxDynamicSharedMemorySize, sm_gu);

    const int gblocks = (E + 127) / 128;

    // rbf basis paths
    rb8_kernel<<<(E + 255) / 256, 256>>>(rbf, W_rbf1, rb8, E);
    rbfh_kernel<<<(E + 31) / 32, HH>>>(rb8, rbf, W_rbf2, W_rbf, rbfh, rbfh2, E);

    // x_ji = silu(e1 @ W_ji + b_ji)
    gemm_rt<HH, HH><<<gblocks, 256, sm_g128>>>(e1, W_ji, b_ji, nullptr, nullptr, xji, nullptr, nullptr, E, 1);
    // A = silu(e1 @ W_kj + b_kj) * rbfh
    gemm_rt<HH, HH><<<gblocks, 256, sm_g128>>>(e1, W_kj, b_kj, rbfh, nullptr, A, nullptr, nullptr, E, 1);
    // xdown = silu(A @ W_down)
    gemm_rt<HH, IC><<<gblocks, 128, sm_gd>>>(A, W_down, nullptr, nullptr, nullptr, xdown, nullptr, nullptr, E, 1);

    // zero accumulator
    zero4_kernel<<<(E * IC / 4 + 255) / 256, 256>>>((float4*)acc, E * IC / 4);

    // T-space projections
    proj8_kernel<TK, 320><<<2048, 256>>>(tt, W_t1, t8, T);
    proj8_kernel<SBFK, 64><<<2048, 256>>>(sbf, W_sbf1, s8, T);

    // gather * sbf_h * t_h, scatter-add by idx_ji
    triplet_kernel<<<2368, 256>>>(t8, s8, W_t2, W_sbf2, xdown, idx_kj, idx_ji, acc, T);

    // A = silu(acc @ W_up) + x_ji
    gemm_rt<IC, HH><<<gblocks, 256, sm_gu>>>(acc, W_up, nullptr, nullptr, xji, A, nullptr, nullptr, E, 1);

    // residual before (1 layer)
    gemm_rt<HH, HH><<<gblocks, 256, sm_g128>>>(A, Wb1, bb1, nullptr, nullptr, B, nullptr, nullptr, E, 1);
    gemm_rt<HH, HH><<<gblocks, 256, sm_g128>>>(B, Wb2, bb2, nullptr, A, C, nullptr, nullptr, E, 1);

    // h = silu(C @ W_lin + b_lin) + e1
    gemm_rt<HH, HH><<<gblocks, 256, sm_g128>>>(C, W_lin, b_lin, nullptr, e1, A, nullptr, nullptr, E, 1);

    // residual after layer 0
    gemm_rt<HH, HH><<<gblocks, 256, sm_g128>>>(A, Wa1, ba1, nullptr, nullptr, B, nullptr, nullptr, E, 1);
    gemm_rt<HH, HH><<<gblocks, 256, sm_g128>>>(B, Wa2, ba2, nullptr, A, C, nullptr, nullptr, E, 1);
    // residual after layer 1 -> final outputs (e1_out, e2_out = e1_out * rbfh2)
    gemm_rt<HH, HH><<<gblocks, 256, sm_g128>>>(C, Wa1 + HH * HH, ba1 + HH, nullptr, nullptr, B, nullptr, nullptr, E, 1);
    gemm_rt<HH, HH><<<gblocks, 256, sm_g128>>>(B, Wa2 + HH * HH, ba2 + HH, nullptr, C, out_e1, rbfh2, out_e2, E, 1);
}

// round 3
// speedup vs baseline: 1.8795x; 1.0351x over previous
#include <cuda_runtime.h>
#include <math.h>

#define EN_MAX 200000
#define TN_MAX 600000
#define HH 128
#define IC 64
#define BSZ 8
#define NRAD 6
#define SBFK 42
#define TK 294

// ---------------- scratch (device globals; no allocations) ----------------
__device__ float g_xji[EN_MAX * HH];
__device__ float g_rbfh[EN_MAX * HH];
__device__ float g_rbfh2[EN_MAX * HH];
__device__ float g_rb8[EN_MAX * BSZ];
__device__ float g_xdown[EN_MAX * IC];
__device__ float g_acc[EN_MAX * IC];
__device__ float g_t8[TN_MAX * BSZ];
__device__ float g_s8[TN_MAX * BSZ];
__device__ float g_bufA[EN_MAX * HH];
__device__ float g_bufB[EN_MAX * HH];
__device__ float g_bufC[EN_MAX * HH];

__device__ __forceinline__ float silu_f(float x) {
    return x / (1.0f + __expf(-x));
}

// packed f32x2 helpers (FFMA2 path — ptxas never auto-fuses; PTX only)
__device__ __forceinline__ void ffma2(unsigned long long& c, unsigned long long a, unsigned long long b) {
    asm("fma.rn.f32x2 %0, %1, %2, %0;" : "+l"(c) : "l"(a), "l"(b));
}
__device__ __forceinline__ unsigned long long dup2(float x) {
    unsigned long long r;
    const unsigned int u = __float_as_uint(x);
    asm("mov.b64 %0, {%1, %1};" : "=l"(r) : "r"(u));
    return r;
}
__device__ __forceinline__ void unpack2(unsigned long long v, float& lo, float& hi) {
    unsigned int a, b;
    asm("mov.b64 {%0, %1}, %2;" : "=r"(a), "=r"(b) : "l"(v));
    lo = __uint_as_float(a);
    hi = __uint_as_float(b);
}

// ---------------- register-tiled row-wise GEMM + epilogue (FFMA2) ----------
// out[row, j] = epi( sum_k in[row,k] * W[k,j] )
// Block computes 128 x NOUT; each thread an 8x8 tile held as 8x4 f32x2 pairs.
template <int KIN, int NOUT>
__global__ void __launch_bounds__(NOUT * 2, 2)
gemm_rt(const float* __restrict__ in,
        const float* __restrict__ W,
        const float* __restrict__ bias,
        const float* __restrict__ mulv,
        const float* __restrict__ addv,
        float* __restrict__ out,
        const float* __restrict__ mul2,
        float* __restrict__ out2,
        int nrows, int act)
{
    constexpr int THREADS = NOUT * 2;        // 256 (NOUT=128) or 128 (NOUT=64)
    constexpr int KB = 64;                   // k-chunk
    constexpr int NC = KIN / KB;             // 2 or 1
    constexpr int APITCH = 132;
    constexpr int TPR = THREADS / 128;       // threads per staged A row
    constexpr int KSPAN = KB / TPR;

    extern __shared__ float sm[];
    float* As = sm;                          // [KB][APITCH] k-major
    float* Bs = sm + KB * APITCH;            // [KB][NOUT]

    const int tid = threadIdx.x;
    const int tr = tid / (NOUT / 8);         // thread row group (0..15)
    const int tc = tid % (NOUT / 8);         // thread col group
    const int r0 = blockIdx.x * 128;

    unsigned long long acc2[8][4];
    #pragma unroll
    for (int i = 0; i < 8; ++i)
        #pragma unroll
        for (int p = 0; p < 4; ++p) acc2[i][p] = 0ull;   // bit pattern of {0.f,0.f}

    #pragma unroll
    for (int c = 0; c < NC; ++c) {
        const int c0 = c * KB;
        if (c) __syncthreads();

        // stage A chunk transposed (k-major)
        {
            const int row = tid / TPR;
            const int part = tid % TPR;
            int rclamp = r0 + row;
            if (rclamp >= nrows) rclamp = nrows - 1;
            const float* src = in + (size_t)rclamp * KIN + c0 + part * KSPAN;
            #pragma unroll
            for (int f = 0; f < KSPAN / 4; ++f) {
                const float4 v = *reinterpret_cast<const float4*>(src + f * 4);
                const int kk = part * KSPAN + f * 4;
                As[(kk + 0) * APITCH + row] = v.x;
                As[(kk + 1) * APITCH + row] = v.y;
                As[(kk + 2) * APITCH + row] = v.z;
                As[(kk + 3) * APITCH + row] = v.w;
            }
        }
        // stage B chunk (row-major [KB][NOUT])
        {
            const float4* Wsrc = reinterpret_cast<const float4*>(W + (size_t)c0 * NOUT);
            float4* Bd = reinterpret_cast<float4*>(Bs);
            #pragma unroll
            for (int i = tid; i < KB * NOUT / 4; i += THREADS)
                Bd[i] = Wsrc[i];
        }
        __syncthreads();

        #pragma unroll 4
        for (int k = 0; k < KB; ++k) {
            const float4 a0 = *reinterpret_cast<const float4*>(&As[k * APITCH + tr * 8]);
            const float4 a1 = *reinterpret_cast<const float4*>(&As[k * APITCH + tr * 8 + 4]);
            const ulonglong2 bA = *reinterpret_cast<const ulonglong2*>(&Bs[k * NOUT + tc * 8]);
            const ulonglong2 bB = *reinterpret_cast<const ulonglong2*>(&Bs[k * NOUT + tc * 8 + 4]);
            const float a[8] = {a0.x, a0.y, a0.z, a0.w, a1.x, a1.y, a1.z, a1.w};
            #pragma unroll
            for (int i = 0; i < 8; ++i) {
                const unsigned long long ap = dup2(a[i]);
                ffma2(acc2[i][0], ap, bA.x);
                ffma2(acc2[i][1], ap, bA.y);
                ffma2(acc2[i][2], ap, bB.x);
                ffma2(acc2[i][3], ap, bB.y);
            }
        }
    }

    // epilogue
    float bv[8];
    if (bias) {
        const float4 v0 = *reinterpret_cast<const float4*>(bias + tc * 8);
        const float4 v1 = *reinterpret_cast<const float4*>(bias + tc * 8 + 4);
        bv[0]=v0.x; bv[1]=v0.y; bv[2]=v0.z; bv[3]=v0.w;
        bv[4]=v1.x; bv[5]=v1.y; bv[6]=v1.z; bv[7]=v1.w;
    } else {
        #pragma unroll
        for (int j = 0; j < 8; ++j) bv[j] = 0.f;
    }

    #pragma unroll
    for (int i = 0; i < 8; ++i) {
        const int row = r0 + tr * 8 + i;
        if (row >= nrows) break;
        const size_t o = (size_t)row * NOUT + tc * 8;
        float v[8];
        #pragma unroll
        for (int p = 0; p < 4; ++p)
            unpack2(acc2[i][p], v[2 * p], v[2 * p + 1]);
        #pragma unroll
        for (int j = 0; j < 8; ++j) {
            float x = v[j] + bv[j];
            if (act) x = silu_f(x);
            v[j] = x;
        }
        if (mulv) {
            const float4 m0 = *reinterpret_cast<const float4*>(mulv + o);
            const float4 m1 = *reinterpret_cast<const float4*>(mulv + o + 4);
            v[0]*=m0.x; v[1]*=m0.y; v[2]*=m0.z; v[3]*=m0.w;
            v[4]*=m1.x; v[5]*=m1.y; v[6]*=m1.z; v[7]*=m1.w;
        }
        if (addv) {
            const float4 s0 = *reinterpret_cast<const float4*>(addv + o);
            const float4 s1 = *reinterpret_cast<const float4*>(addv + o + 4);
            v[0]+=s0.x; v[1]+=s0.y; v[2]+=s0.z; v[3]+=s0.w;
            v[4]+=s1.x; v[5]+=s1.y; v[6]+=s1.z; v[7]+=s1.w;
        }
        *reinterpret_cast<float4*>(out + o)     = make_float4(v[0], v[1], v[2], v[3]);
        *reinterpret_cast<float4*>(out + o + 4) = make_float4(v[4], v[5], v[6], v[7]);
        if (out2) {
            const float4 m0 = *reinterpret_cast<const float4*>(mul2 + o);
            const float4 m1 = *reinterpret_cast<const float4*>(mul2 + o + 4);
            *reinterpret_cast<float4*>(out2 + o)     = make_float4(v[0]*m0.x, v[1]*m0.y, v[2]*m0.z, v[3]*m0.w);
            *reinterpret_cast<float4*>(out2 + o + 4) = make_float4(v[4]*m1.x, v[5]*m1.y, v[6]*m1.z, v[7]*m1.w);
        }
    }
}

// ---------------- rbf basis helpers ----------------
__global__ void rb8_kernel(const float* __restrict__ rbf, const float* __restrict__ W1,
                           float* __restrict__ out, int n)
{
    const int e = blockIdx.x * blockDim.x + threadIdx.x;
    if (e >= n) return;
    float r[NRAD];
    #pragma unroll
    for (int i = 0; i < NRAD; ++i) r[i] = rbf[(size_t)e * NRAD + i];
    #pragma unroll
    for (int b = 0; b < BSZ; ++b) {
        float s = 0.f;
        #pragma unroll
        for (int i = 0; i < NRAD; ++i) s += r[i] * __ldg(&W1[i * BSZ + b]);
        out[(size_t)e * BSZ + b] = s;
    }
}

__global__ void rbfh_kernel(const float* __restrict__ rb8, const float* __restrict__ rbf,
                            const float* __restrict__ W_rbf2, const float* __restrict__ W_rbf,
                            float* __restrict__ rbfh, float* __restrict__ rbfh2, int n)
{
    __shared__ float w2[BSZ * HH];
    __shared__ float wr[NRAD * HH];
    const int j = threadIdx.x;
    #pragma unroll
    for (int b = 0; b < BSZ; ++b) w2[b * HH + j] = W_rbf2[b * HH + j];
    #pragma unroll
    for (int r = 0; r < NRAD; ++r) wr[r * HH + j] = W_rbf[r * HH + j];
    __syncthreads();

    const int row0 = blockIdx.x * 32;
    for (int rr = 0; rr < 32; ++rr) {
        const int row = row0 + rr;
        if (row >= n) return;
        const float4* rp = reinterpret_cast<const float4*>(rb8 + (size_t)row * BSZ);
        const float4 ra = __ldg(rp), rb = __ldg(rp + 1);
        float a1 = ra.x * w2[0 * HH + j] + ra.y * w2[1 * HH + j] +
                   ra.z * w2[2 * HH + j] + ra.w * w2[3 * HH + j] +
                   rb.x * w2[4 * HH + j] + rb.y * w2[5 * HH + j] +
                   rb.z * w2[6 * HH + j] + rb.w * w2[7 * HH + j];
        float a2 = 0.f;
        #pragma unroll
        for (int r = 0; r < NRAD; ++r) a2 += __ldg(&rbf[(size_t)row * NRAD + r]) * wr[r * HH + j];
        rbfh[(size_t)row * HH + j]  = a1;
        rbfh2[(size_t)row * HH + j] = a2;
    }
}

// ---------------- T-space: X[T,K] @ W1[K,8] -> out8[T,8] ----------------
template <int K, int PK>
__global__ void proj8_kernel(const float* __restrict__ X, const float* __restrict__ W1,
                             float* __restrict__ out8, int nrows)
{
    __shared__ float wcm[BSZ * PK];
    __shared__ float red[8][32 * 33];
    const int tid = threadIdx.x;
    for (int x = tid; x < BSZ * PK; x += blockDim.x) wcm[x] = 0.f;
    __syncthreads();
    for (int x = tid; x < K * BSZ; x += blockDim.x) {
        const int i = x / BSZ, b = x % BSZ;
        wcm[b * PK + i] = W1[x];
    }
    __syncthreads();

    const int warp = tid >> 5, lane = tid & 31;
    float* myred = &red[warp][0];
    const int nw = blockDim.x >> 5;
    constexpr int ITERS = (K + 31) / 32;

    for (int r0 = (blockIdx.x * nw + warp) * 4; r0 < nrows; r0 += gridDim.x * nw * 4) {
        float acc[4][BSZ] = {};
        const float* x0 = X + (size_t)r0 * K;
        #pragma unroll
        for (int k = 0; k < ITERS; ++k) {
            const int i = lane + k * 32;
            float xv[4] = {0.f, 0.f, 0.f, 0.f};
            if (i < K) {
                #pragma unroll
                for (int rr = 0; rr < 4; ++rr) xv[rr] = x0[(size_t)rr * K + i];
            }
            #pragma unroll
            for (int b = 0; b < BSZ; ++b) {
                const float w = wcm[b * PK + i];
                #pragma unroll
                for (int rr = 0; rr < 4; ++rr) acc[rr][b] += w * xv[rr];
            }
        }
        #pragma unroll
        for (int rr = 0; rr < 4; ++rr)
            #pragma unroll
            for (int b = 0; b < BSZ; ++b)
                myred[lane * 33 + rr * BSZ + b] = acc[rr][b];
        __syncwarp();
        float s = 0.f;
        #pragma unroll
        for (int l = 0; l < 32; ++l) s += myred[l * 33 + lane];
        out8[(size_t)r0 * BSZ + lane] = s;
        __syncwarp();
    }
}

// ---------------- triplet gather/scale/scatter ----------------
__global__ void triplet_kernel(const float* __restrict__ t8, const float* __restrict__ s8,
                               const float* __restrict__ W_t2, const float* __restrict__ W_sbf2,
                               const float* __restrict__ xdown,
                               const int* __restrict__ idx_kj, const int* __restrict__ idx_ji,
                               float* __restrict__ acc, int nt)
{
    __shared__ float wt2s[BSZ * IC];
    __shared__ float ws2s[BSZ * IC];
    const int tid = threadIdx.x;
    for (int i = tid; i < BSZ * IC; i += blockDim.x) { wt2s[i] = W_t2[i]; ws2s[i] = W_sbf2[i]; }
    __syncthreads();

    const int warp = tid >> 5, lane = tid & 31;
    const int total_warps = (blockDim.x * gridDim.x) >> 5;

    for (int tr = blockIdx.x * (blockDim.x >> 5) + warp; tr < nt; tr += total_warps) {
        const float4* tp = reinterpret_cast<const float4*>(t8 + (size_t)tr * BSZ);
        const float4 ta = __ldg(tp), tb = __ldg(tp + 1);
        const float4* sp = reinterpret_cast<const float4*>(s8 + (size_t)tr * BSZ);
        const float4 sa = __ldg(sp), sb = __ldg(sp + 1);
        const float tv[BSZ] = {ta.x, ta.y, ta.z, ta.w, tb.x, tb.y, tb.z, tb.w};
        const float sv[BSZ] = {sa.x, sa.y, sa.z, sa.w, sb.x, sb.y, sb.z, sb.w};
        const int kj = idx_kj[tr], ji = idx_ji[tr];
        const int c0 = lane, c1 = lane + 32;
        float t0 = 0.f, t1 = 0.f, s0 = 0.f, s1 = 0.f;
        #pragma unroll
        for (int b = 0; b < BSZ; ++b) {
            t0 += tv[b] * wt2s[b * IC + c0];
            t1 += tv[b] * wt2s[b * IC + c1];
            s0 += sv[b] * ws2s[b * IC + c0];
            s1 += sv[b] * ws2s[b * IC + c1];
        }
        const float g0 = xdown[(size_t)kj * IC + c0];
        const float g1 = xdown[(size_t)kj * IC + c1];
        atomicAdd(acc + (size_t)ji * IC + c0, g0 * t0 * s0);
        atomicAdd(acc + (size_t)ji * IC + c1, g1 * t1 * s1);
    }
}

__global__ void zero4_kernel(float4* __restrict__ p, int n4)
{
    const int i = blockIdx.x * blockDim.x + threadIdx.x;
    if (i < n4) p[i] = make_float4(0.f, 0.f, 0.f, 0.f);
}

// ---------------- launch ----------------
extern "C" void kernel_launch(void* const* d_in, const int* in_sizes, int n_in,
                              void* d_out, int out_size)
{
    const float* e1     = (const float*)d_in[0];
    const float* rbf    = (const float*)d_in[1];
    const float* sbf    = (const float*)d_in[2];
    const float* tt     = (const float*)d_in[3];
    const int*   idx_kj = (const int*)d_in[4];
    const int*   idx_ji = (const int*)d_in[5];
    const float* W_rbf1 = (const float*)d_in[6];
    const float* W_rbf2 = (const float*)d_in[7];
    const float* W_sbf1 = (const float*)d_in[8];
    const float* W_sbf2 = (const float*)d_in[9];
    const float* W_t1   = (const float*)d_in[10];
    const float* W_t2   = (const float*)d_in[11];
    const float* W_rbf  = (const float*)d_in[12];
    const float* W_kj   = (const float*)d_in[13];
    const float* b_kj   = (const float*)d_in[14];
    const float* W_ji   = (const float*)d_in[15];
    const float* b_ji   = (const float*)d_in[16];
    const float* W_down = (const float*)d_in[17];
    const float* W_up   = (const float*)d_in[18];
    const float* Wb1    = (const float*)d_in[19];
    const float* bb1    = (const float*)d_in[20];
    const float* Wb2    = (const float*)d_in[21];
    const float* bb2    = (const float*)d_in[22];
    const float* W_lin  = (const float*)d_in[23];
    const float* b_lin  = (const float*)d_in[24];
    const float* Wa1    = (const float*)d_in[25];
    const float* ba1    = (const float*)d_in[26];
    const float* Wa2    = (const float*)d_in[27];
    const float* ba2    = (const float*)d_in[28];

    const int E = in_sizes[0] / HH;
    const int T = in_sizes[4];

    float *xji, *rbfh, *rbfh2, *rb8, *xdown, *acc, *t8, *s8, *A, *B, *C;
    cudaGetSymbolAddress((void**)&xji,   g_xji);
    cudaGetSymbolAddress((void**)&rbfh,  g_rbfh);
    cudaGetSymbolAddress((void**)&rbfh2, g_rbfh2);
    cudaGetSymbolAddress((void**)&rb8,   g_rb8);
    cudaGetSymbolAddress((void**)&xdown, g_xdown);
    cudaGetSymbolAddress((void**)&acc,   g_acc);
    cudaGetSymbolAddress((void**)&t8,    g_t8);
    cudaGetSymbolAddress((void**)&s8,    g_s8);
    cudaGetSymbolAddress((void**)&A,     g_bufA);
    cudaGetSymbolAddress((void**)&B,     g_bufB);
    cudaGetSymbolAddress((void**)&C,     g_bufC);

    float* out_e1 = (float*)d_out;
    float* out_e2 = (float*)d_out + (size_t)E * HH;

    // dynamic smem: As[64][132] + Bs[64][NOUT]
    const int sm_g128 = 64 * 132 * 4 + 64 * 128 * 4;   // 66560
    const int sm_gd   = 64 * 132 * 4 + 64 * 64 * 4;    // 50176
    const int sm_gu   = 64 * 132 * 4 + 64 * 128 * 4;   // 66560
    cudaFuncSetAttribute(gemm_rt<HH, HH>, cudaFuncAttributeMaxDynamicSharedMemorySize, sm_g128);
    cudaFuncSetAttribute(gemm_rt<HH, IC>, cudaFuncAttributeMaxDynamicSharedMemorySize, sm_gd);
    cudaFuncSetAttribute(gemm_rt<IC, HH>, cudaFuncAttributeMaxDynamicSharedMemorySize, sm_gu);

    const int gblocks = (E + 127) / 128;

    // rbf basis paths
    rb8_kernel<<<(E + 255) / 256, 256>>>(rbf, W_rbf1, rb8, E);
    rbfh_kernel<<<(E + 31) / 32, HH>>>(rb8, rbf, W_rbf2, W_rbf, rbfh, rbfh2, E);

    // x_ji = silu(e1 @ W_ji + b_ji)
    gemm_rt<HH, HH><<<gblocks, 256, sm_g128>>>(e1, W_ji, b_ji, nullptr, nullptr, xji, nullptr, nullptr, E, 1);
    // A = silu(e1 @ W_kj + b_kj) * rbfh
    gemm_rt<HH, HH><<<gblocks, 256, sm_g128>>>(e1, W_kj, b_kj, rbfh, nullptr, A, nullptr, nullptr, E, 1);
    // xdown = silu(A @ W_down)
    gemm_rt<HH, IC><<<gblocks, 128, sm_gd>>>(A, W_down, nullptr, nullptr, nullptr, xdown, nullptr, nullptr, E, 1);

    // zero accumulator
    zero4_kernel<<<(E * IC / 4 + 255) / 256, 256>>>((float4*)acc, E * IC / 4);

    // T-space projections
    proj8_kernel<TK, 320><<<2048, 256>>>(tt, W_t1, t8, T);
    proj8_kernel<SBFK, 64><<<2048, 256>>>(sbf, W_sbf1, s8, T);

    // gather * sbf_h * t_h, scatter-add by idx_ji
    triplet_kernel<<<2368, 256>>>(t8, s8, W_t2, W_sbf2, xdown, idx_kj, idx_ji, acc, T);

    // A = silu(acc @ W_up) + x_ji
    gemm_rt<IC, HH><<<gblocks, 256, sm_gu>>>(acc, W_up, nullptr, nullptr, xji, A, nullptr, nullptr, E, 1);

    // residual before (1 layer)
    gemm_rt<HH, HH><<<gblocks, 256, sm_g128>>>(A, Wb1, bb1, nullptr, nullptr, B, nullptr, nullptr, E, 1);
    gemm_rt<HH, HH><<<gblocks, 256, sm_g128>>>(B, Wb2, bb2, nullptr, A, C, nullptr, nullptr, E, 1);

    // h = silu(C @ W_lin + b_lin) + e1
    gemm_rt<HH, HH><<<gblocks, 256, sm_g128>>>(C, W_lin, b_lin, nullptr, e1, A, nullptr, nullptr, E, 1);

    // residual after layer 0
    gemm_rt<HH, HH><<<gblocks, 256, sm_g128>>>(A, Wa1, ba1, nullptr, nullptr, B, nullptr, nullptr, E, 1);
    gemm_rt<HH, HH><<<gblocks, 256, sm_g128>>>(B, Wa2, ba2, nullptr, A, C, nullptr, nullptr, E, 1);
    // residual after layer 1 -> final outputs (e1_out, e2_out = e1_out * rbfh2)
    gemm_rt<HH, HH><<<gblocks, 256, sm_g128>>>(C, Wa1 + HH * HH, ba1 + HH, nullptr, nullptr, B, nullptr, nullptr, E, 1);
    gemm_rt<HH, HH><<<gblocks, 256, sm_g128>>>(B, Wa2 + HH * HH, ba2 + HH, nullptr, C, out_e1, rbfh2, out_e2, E, 1);
}